// round 17
// baseline (speedup 1.0000x reference)
#include <cuda_runtime.h>

// Problem constants
#define BB      8
#define DIN     1024
#define TT      2048
#define KCB     8192
#define CD      8
#define NTOK    (BB*TT)            // 16384
#define CSPLIT  1024               // codes per search CTA
#define NSPL    (KCB/CSPLIT)       // 8 code splits
#define CHUNKS  (CSPLIT/8)         // 128 mma chunks per warp
#define MARGIN  6e-3f              // tf32->fp32 score bound (~1e-3) x 6 safety

// Output buffer layout (float32, concatenated tuple)
#define OUT_OFF   0
#define LOSS_OFF  (BB*DIN*TT)                 // 16777216
#define IDX_OFF   (LOSS_OFF + 16)             // 16777232
#define ZE_OFF    (IDX_OFF + NTOK)            // 16793616

// Scratch (device globals — no allocation allowed)
__device__ float              g_enc[(size_t)NTOK*CD];  // normalized encodings, token-major
__device__ float2             g_cbt[(size_t)KCB][4];   // tf32-rounded cb: [code][t]={c[t],c[t+4]}
__device__ float              g_cbnf[(size_t)KCB*CD];  // normalized cb, full fp32 (re-rank)
__device__ float              g_c2h[KCB];              // -0.5*||cb_n||^2 (re-rank init)
__device__ unsigned long long g_wdup[(size_t)DIN*9];   // per out-row: 8x {w,w} + {b,b}
__device__ unsigned long long g_best[NTOK];            // atomicMax key: (mono(score)<<32)|(8191-idx)
__device__ unsigned int       g_tmax[NTOK];            // per-token tf32 max (mono32)
__device__ unsigned long long g_zq2[CD][NTOK/2];       // z_q pair-packed: [k][tokpair]

// ---- packed f32x2 helpers ----
__device__ __forceinline__ unsigned long long pack2(float lo, float hi) {
    unsigned long long r;
    asm("mov.b64 %0, {%1,%2};" : "=l"(r) : "f"(lo), "f"(hi));
    return r;
}
__device__ __forceinline__ void unpack2(unsigned long long v, float& lo, float& hi) {
    asm("mov.b64 {%0,%1}, %2;" : "=f"(lo), "=f"(hi) : "l"(v));
}
__device__ __forceinline__ unsigned long long fma2(unsigned long long a, unsigned long long b,
                                                   unsigned long long c) {
    unsigned long long d;
    asm("fma.rn.f32x2 %0, %1, %2, %3;" : "=l"(d) : "l"(a), "l"(b), "l"(c));
    return d;
}
__device__ __forceinline__ unsigned long long add2(unsigned long long a, unsigned long long b) {
    unsigned long long d;
    asm("add.rn.f32x2 %0, %1, %2;" : "=l"(d) : "l"(a), "l"(b));
    return d;
}

// ---- tf32 helpers ----
__device__ __forceinline__ unsigned tf32cvt(float x) {
    unsigned r;
    asm("cvt.rna.tf32.f32 %0, %1;" : "=r"(r) : "f"(x));
    return r;
}
__device__ __forceinline__ void mma_tf32(float& d0, float& d1, float& d2, float& d3,
                                         unsigned a0, unsigned a1, unsigned a2, unsigned a3,
                                         unsigned b0, unsigned b1) {
    float z = 0.0f;
    asm volatile(
        "mma.sync.aligned.m16n8k8.row.col.f32.tf32.tf32.f32 "
        "{%0,%1,%2,%3},{%4,%5,%6,%7},{%8,%9},{%10,%11,%12,%13};"
        : "=f"(d0), "=f"(d1), "=f"(d2), "=f"(d3)
        : "r"(a0), "r"(a1), "r"(a2), "r"(a3), "r"(b0), "r"(b1),
          "f"(z), "f"(z), "f"(z), "f"(z));
}

// Monotonic keys: unsigned compare == float compare.
__device__ __forceinline__ unsigned mono32(float s) {
    unsigned u = __float_as_uint(s);
    return u ^ ((unsigned)((int)u >> 31) | 0x80000000u);
}
__device__ __forceinline__ float unmono32(unsigned m) {
    unsigned u = (m & 0x80000000u) ? (m ^ 0x80000000u) : ~m;
    return __uint_as_float(u);
}
// 64-bit key: (mono(score)<<32) | (8191-idx) -> tie = smallest index (first-wins).
__device__ __forceinline__ unsigned long long mkkey(float s, int gidx) {
    return ((unsigned long long)mono32(s) << 32) | (unsigned)(KCB - 1 - gidx);
}

// ---------------------------------------------------------------------------
// Prep (folded into k_inproj prologue): normalize codebook -> tf32 table +
// fp32 re-rank table; pack w_out/b_out; zero losses, g_best, g_tmax.
// ---------------------------------------------------------------------------
__device__ __forceinline__ void do_prep_item(int i, const float* __restrict__ cb,
                                             const float* __restrict__ w_out,
                                             const float* __restrict__ b_out,
                                             float* __restrict__ out) {
    if (i < KCB) {
        float v[CD];
#pragma unroll
        for (int k = 0; k < CD; k++) v[k] = cb[(size_t)i * CD + k];
        float s = 0.0f;
#pragma unroll
        for (int k = 0; k < CD; k++) s += v[k] * v[k];
        float den = fmaxf(__fsqrt_rn(s), 1e-12f);
        float nv[CD];
#pragma unroll
        for (int k = 0; k < CD; k++) nv[k] = __fdiv_rn(v[k], den);
        float c2 = 0.0f;
#pragma unroll
        for (int k = 0; k < CD; k++) c2 += nv[k] * nv[k];
#pragma unroll
        for (int k = 0; k < CD; k++) g_cbnf[(size_t)i * CD + k] = nv[k];
        g_c2h[i] = -0.5f * c2;
#pragma unroll
        for (int t = 0; t < 4; t++) {
            float2 p;
            p.x = __uint_as_float(tf32cvt(nv[t]));
            p.y = __uint_as_float(tf32cvt(nv[t + 4]));
            g_cbt[i][t] = p;
        }
    } else if (i < KCB + DIN) {
        int o = i - KCB;
#pragma unroll
        for (int k = 0; k < CD; k++) {
            float w = w_out[(size_t)o * CD + k];
            g_wdup[(size_t)o * 9 + k] = pack2(w, w);
        }
        float bo = b_out[o];
        g_wdup[(size_t)o * 9 + 8] = pack2(bo, bo);
    } else if (i < KCB + DIN + 16) {
        out[LOSS_OFF + (i - KCB - DIN)] = 0.0f;
    } else if (i < KCB + DIN + 16 + NTOK) {
        g_best[i - KCB - DIN - 16] = 0ull;    // below any real key
    } else if (i < KCB + DIN + 16 + 2 * NTOK) {
        g_tmax[i - KCB - DIN - 16 - NTOK] = 0u;
    }
}

// ---------------------------------------------------------------------------
// K1 (fused): prep prologue + in-projection + bias + z_e store + L2-normalize.
// grid (T/16, B) = 1024 CTAs, 256 threads.  CTA = 16 tokens x full D=1024.
// ---------------------------------------------------------------------------
__global__ void __launch_bounds__(256) k_inproj(const float* __restrict__ z,
                                                const float* __restrict__ w_in,
                                                const float* __restrict__ b_in,
                                                const float* __restrict__ cb,
                                                const float* __restrict__ w_out,
                                                const float* __restrict__ b_out,
                                                float* __restrict__ out) {
    __shared__ float sw[DIN * 8];                        // [d][o]  32 KB
    __shared__ unsigned long long sred[8][16][4];        // [warp][tok][pack] 4 KB

    int tid = threadIdx.x;

    // --- prep prologue: first 42K global threads each handle one item ---
    {
        int bid = blockIdx.y * gridDim.x + blockIdx.x;   // 0..1023
        int gid = bid * 256 + tid;
        if (gid < KCB + DIN + 16 + 2 * NTOK)
            do_prep_item(gid, cb, w_out, b_out, out);
    }

    for (int i = tid; i < DIN * 8; i += 256) {
        int o = i >> 10, d = i & 1023;
        sw[d * 8 + o] = w_in[i];
    }
    __syncthreads();

    int lane = tid & 31, warp = tid >> 5;
    int tokl = lane & 15;
    int segh = lane >> 4;                 // 0/1
    int seg = warp * 2 + segh;            // 0..15, 64 d each
    int b = blockIdx.y;
    int t = blockIdx.x * 16 + tokl;

    unsigned long long a01 = 0, a23 = 0, a45 = 0, a67 = 0;
    const float* zp = z + ((size_t)b * DIN + (size_t)seg * 64) * TT + t;
    const float* swp = &sw[seg * 64 * 8];
#pragma unroll 8
    for (int dd = 0; dd < 64; dd++) {
        float zv = zp[(size_t)dd * TT];
        unsigned long long zd = pack2(zv, zv);
        const ulonglong2* wp = reinterpret_cast<const ulonglong2*>(&swp[dd * 8]);
        ulonglong2 wA = wp[0], wB = wp[1];
        a01 = fma2(zd, wA.x, a01);
        a23 = fma2(zd, wA.y, a23);
        a45 = fma2(zd, wB.x, a45);
        a67 = fma2(zd, wB.y, a67);
    }
    a01 = add2(a01, __shfl_xor_sync(0xffffffffu, a01, 16));
    a23 = add2(a23, __shfl_xor_sync(0xffffffffu, a23, 16));
    a45 = add2(a45, __shfl_xor_sync(0xffffffffu, a45, 16));
    a67 = add2(a67, __shfl_xor_sync(0xffffffffu, a67, 16));
    if (segh == 0) {
        sred[warp][tokl][0] = a01; sred[warp][tokl][1] = a23;
        sred[warp][tokl][2] = a45; sred[warp][tokl][3] = a67;
    }
    __syncthreads();

    if (tid < 64) {
        int pk = tid & 3;        // channel pair {2pk, 2pk+1}
        int tk = tid >> 2;       // token slot 0..15
        unsigned long long s = sred[0][tk][pk];
#pragma unroll
        for (int w = 1; w < 8; w++) s = add2(s, sred[w][tk][pk]);
        float lo, hi;
        unpack2(s, lo, hi);
        lo += b_in[2 * pk];
        hi += b_in[2 * pk + 1];

        int tt = blockIdx.x * 16 + tk;
        out[ZE_OFF + ((size_t)b * 8 + 2 * pk) * TT + tt]     = lo;
        out[ZE_OFF + ((size_t)b * 8 + 2 * pk + 1) * TT + tt] = hi;

        float s2 = lo * lo + hi * hi;
        s2 += __shfl_xor_sync(0xffffffffu, s2, 1);
        s2 += __shfl_xor_sync(0xffffffffu, s2, 2);
        float den = fmaxf(__fsqrt_rn(s2), 1e-12f);
        int token = b * TT + tt;
        reinterpret_cast<unsigned long long*>(&g_enc[(size_t)token * 8])[pk] =
            pack2(__fdiv_rn(lo, den), __fdiv_rn(hi, den));
    }
}

// ---------------------------------------------------------------------------
// K2: search pass 1 — per-token max of tf32 scores via m16n8k8 mma.
// grid (NTOK/128, 8 code-splits) = 1024 CTAs, 256 thr (8 warps x 16 tokens).
// Warp: A = 16 tokens (fixed), loop 128 chunks of 8 codes from smem.
// ---------------------------------------------------------------------------
__global__ void __launch_bounds__(256) k_pass1() {
    __shared__ float2 s_cb[CSPLIT][4];    // 32 KB, tf32-encoded
    int tid = threadIdx.x;
    int cbase = blockIdx.y * CSPLIT;
    {
        const float2* src = &g_cbt[cbase][0];
        float2* dst = &s_cb[0][0];
        for (int i = tid; i < CSPLIT * 4; i += 256) dst[i] = src[i];
    }

    int lane = tid & 31, warp = tid >> 5;
    int g = lane >> 2, tig = lane & 3;
    int tokBase = blockIdx.x * 128 + warp * 16;
    int tokA = tokBase + g, tokB = tokBase + 8 + g;

    unsigned a0 = tf32cvt(g_enc[(size_t)tokA * 8 + tig]);
    unsigned a1 = tf32cvt(g_enc[(size_t)tokB * 8 + tig]);
    unsigned a2 = tf32cvt(g_enc[(size_t)tokA * 8 + tig + 4]);
    unsigned a3 = tf32cvt(g_enc[(size_t)tokB * 8 + tig + 4]);
    __syncthreads();

    float mA = -3.4e38f, mB = -3.4e38f;
#pragma unroll 4
    for (int ch = 0; ch < CHUNKS; ch++) {
        float2 bb = s_cb[ch * 8 + g][tig];
        float d0, d1, d2, d3;
        mma_tf32(d0, d1, d2, d3, a0, a1, a2, a3,
                 __float_as_uint(bb.x), __float_as_uint(bb.y));
        mA = fmaxf(mA, fmaxf(d0, d1));
        mB = fmaxf(mB, fmaxf(d2, d3));
    }
    // combine across the 4 threads (tig) holding the same rows
    mA = fmaxf(mA, __shfl_xor_sync(0xffffffffu, mA, 1));
    mA = fmaxf(mA, __shfl_xor_sync(0xffffffffu, mA, 2));
    mB = fmaxf(mB, __shfl_xor_sync(0xffffffffu, mB, 1));
    mB = fmaxf(mB, __shfl_xor_sync(0xffffffffu, mB, 2));
    if (tig == 0) {
        atomicMax(&g_tmax[tokA], mono32(mA));
        atomicMax(&g_tmax[tokB], mono32(mB));
    }
}

// ---------------------------------------------------------------------------
// Exact fp32 re-rank of one (token, code) candidate — identical fma chain
// (ascending k, init -0.5*c2) to the previous passing scalar kernel.
// ---------------------------------------------------------------------------
__device__ __noinline__ void rerank(int token, int code) {
    const float* e = &g_enc[(size_t)token * 8];
    const float* c = &g_cbnf[(size_t)code * 8];
    float s = g_c2h[code];
#pragma unroll
    for (int k = 0; k < 8; k++) s = fmaf(e[k], c[k], s);
    atomicMax(&g_best[token], mkkey(s, code));
}

// ---------------------------------------------------------------------------
// K3: search pass 2 — recompute tf32 scores; candidates within MARGIN of the
// token max get exact fp32 re-rank into g_best.  True argmax provably
// qualifies (|s - s_tf32| <= ~1e-3 << MARGIN).
// ---------------------------------------------------------------------------
__global__ void __launch_bounds__(256) k_pass2() {
    __shared__ float2 s_cb[CSPLIT][4];
    int tid = threadIdx.x;
    int cbase = blockIdx.y * CSPLIT;
    {
        const float2* src = &g_cbt[cbase][0];
        float2* dst = &s_cb[0][0];
        for (int i = tid; i < CSPLIT * 4; i += 256) dst[i] = src[i];
    }

    int lane = tid & 31, warp = tid >> 5;
    int g = lane >> 2, tig = lane & 3;
    int tokBase = blockIdx.x * 128 + warp * 16;
    int tokA = tokBase + g, tokB = tokBase + 8 + g;

    unsigned a0 = tf32cvt(g_enc[(size_t)tokA * 8 + tig]);
    unsigned a1 = tf32cvt(g_enc[(size_t)tokB * 8 + tig]);
    unsigned a2 = tf32cvt(g_enc[(size_t)tokA * 8 + tig + 4]);
    unsigned a3 = tf32cvt(g_enc[(size_t)tokB * 8 + tig + 4]);
    float thrA = unmono32(g_tmax[tokA]) - MARGIN;
    float thrB = unmono32(g_tmax[tokB]) - MARGIN;
    __syncthreads();

#pragma unroll 4
    for (int ch = 0; ch < CHUNKS; ch++) {
        float2 bb = s_cb[ch * 8 + g][tig];
        float d0, d1, d2, d3;
        mma_tf32(d0, d1, d2, d3, a0, a1, a2, a3,
                 __float_as_uint(bb.x), __float_as_uint(bb.y));
        int code0 = cbase + ch * 8 + 2 * tig;
        if (d0 >= thrA) rerank(tokA, code0);
        if (d1 >= thrA) rerank(tokA, code0 + 1);
        if (d2 >= thrB) rerank(tokB, code0);
        if (d3 >= thrB) rerank(tokB, code0 + 1);
    }
}

// ---------------------------------------------------------------------------
// K4: z_q staging.  Work-item = (token-pair, channel): 8192 x 8 = 256 CTAs.
// Warp = one channel k x 32 consecutive pairs -> coalesced; codebook picks
// scattered (L1/L2 resident).  k==0 warps also write the indices output.
// ---------------------------------------------------------------------------
__global__ void __launch_bounds__(256) k_zq(const float* __restrict__ cb,
                                            float* __restrict__ out) {
    int lane = threadIdx.x & 31;
    int k = threadIdx.x >> 5;                 // channel 0..7
    int tp = blockIdx.x * 32 + lane;          // pair index 0..8191
    int tok0 = tp * 2;
    int b = tok0 >> 11, t = tok0 & 2047;

    unsigned long long pk0 = g_best[tok0], pk1 = g_best[tok0 + 1];
    int i0 = KCB - 1 - (int)(unsigned)(pk0 & 0xffffffffu);
    int i1 = KCB - 1 - (int)(unsigned)(pk1 & 0xffffffffu);

    if (k == 0) {
        float2 iv;
        iv.x = (float)i0; iv.y = (float)i1;
        *reinterpret_cast<float2*>(&out[IDX_OFF + tok0]) = iv;
    }

    float q0 = cb[(size_t)i0 * CD + k];
    float q1 = cb[(size_t)i1 * CD + k];
    float2 ze = *reinterpret_cast<const float2*>(&out[ZE_OFF + ((size_t)b * 8 + k) * TT + t]);
    g_zq2[k][tp] = pack2(ze.x + (q0 - ze.x), ze.y + (q1 - ze.y));
}

// ---------------------------------------------------------------------------
// K5: out-projection.  grid(T/1024, B, 64 o-splits of 16) = 1024 CTAs,
//     256 threads, 4 tokens/thread (two f32x2 pairs).  LDG.128 zq loads,
//     16 o-rows with bias folded into fma chain init, STG.128 stores.
// ---------------------------------------------------------------------------
__global__ void __launch_bounds__(256, 4) k_outproj(float* __restrict__ out) {
    __shared__ unsigned long long s_w[16][8];
    __shared__ unsigned long long s_b[16];
    int tid = threadIdx.x;
    int ob = blockIdx.z * 16;
    if (tid < 16 * 9) {
        unsigned long long v = g_wdup[(size_t)ob * 9 + tid];
        int j = tid / 9, kk = tid - j * 9;
        if (kk < 8) s_w[j][kk] = v; else s_b[j] = v;
    }

    int b = blockIdx.y;
    int t0 = blockIdx.x * 1024 + tid * 4;
    int tp = (b * TT + t0) >> 1;          // even: two consecutive pairs

    ulonglong2 zq[8];                      // .x = pair A (tok0,1), .y = pair B (tok2,3)
#pragma unroll
    for (int k = 0; k < 8; k++)
        zq[k] = *reinterpret_cast<const ulonglong2*>(&g_zq2[k][tp]);
    __syncthreads();

    float* obase = out + OUT_OFF + ((size_t)b * DIN + ob) * TT + t0;
#pragma unroll 2
    for (int o = 0; o < 16; o++) {
        const ulonglong2* wp = reinterpret_cast<const ulonglong2*>(&s_w[o][0]);
        ulonglong2 wA = wp[0], wB = wp[1], wC = wp[2], wD = wp[3];
        unsigned long long bias = s_b[o];
        unsigned long long aA = fma2(zq[0].x, wA.x, bias);
        unsigned long long aB = fma2(zq[0].y, wA.x, bias);
        aA = fma2(zq[1].x, wA.y, aA);  aB = fma2(zq[1].y, wA.y, aB);
        aA = fma2(zq[2].x, wB.x, aA);  aB = fma2(zq[2].y, wB.x, aB);
        aA = fma2(zq[3].x, wB.y, aA);  aB = fma2(zq[3].y, wB.y, aB);
        aA = fma2(zq[4].x, wC.x, aA);  aB = fma2(zq[4].y, wC.x, aB);
        aA = fma2(zq[5].x, wC.y, aA);  aB = fma2(zq[5].y, wC.y, aB);
        aA = fma2(zq[6].x, wD.x, aA);  aB = fma2(zq[6].y, wD.x, aB);
        aA = fma2(zq[7].x, wD.y, aA);  aB = fma2(zq[7].y, wD.y, aB);
        ulonglong2 st; st.x = aA; st.y = aB;
        *reinterpret_cast<ulonglong2*>(&obase[(size_t)o * TT]) = st;
    }
}

// ---------------------------------------------------------------------------
extern "C" void kernel_launch(void* const* d_in, const int* in_sizes, int n_in,
                              void* d_out, int out_size) {
    const float* z     = (const float*)d_in[0];
    const float* w_in  = (const float*)d_in[1];
    const float* b_in  = (const float*)d_in[2];
    const float* w_out = (const float*)d_in[3];
    const float* b_out = (const float*)d_in[4];
    const float* cb    = (const float*)d_in[5];
    float* out = (float*)d_out;

    dim3 g1(TT / 16, BB);              // (128, 8) = 1024 CTAs, prep folded in
    k_inproj<<<g1, 256>>>(z, w_in, b_in, cb, w_out, b_out, out);

    dim3 gs(NTOK / 128, NSPL);         // (128, 8) = 1024 CTAs per pass
    k_pass1<<<gs, 256>>>();
    k_pass2<<<gs, 256>>>();

    k_zq<<<NTOK / 2 / 32, 256>>>(cb, out);   // 256 CTAs

    dim3 g5(TT / 1024, BB, DIN / 16);  // (2, 8, 64) = 1024 CTAs
    k_outproj<<<g5, 256>>>(out);
}